// round 3
// baseline (speedup 1.0000x reference)
#include <cuda_runtime.h>
#include <math.h>

#define CHANNEL   256
#define MEM_SIZE  684
#define POS_NUM   128
#define NEG_NUM   512
#define CLASS_NUM 60
#define BANK_ROWS 41040          // MEM_SIZE * CLASS_NUM
#define BATCH     512

// ---------------- scratch (static device globals; no allocation at runtime) ---
__device__ float  g_bank[BANK_ROWS * CHANNEL];          // ~42 MB
__device__ float  g_flag[BANK_ROWS];
__device__ float  g_ap[(size_t)BATCH * BANK_ROWS];      // ~84 MB
__device__ double g_partial[BATCH];

// ---------------- order-preserving float <-> uint key --------------------------
__device__ __forceinline__ unsigned key_asc(float x) {
    unsigned u = __float_as_uint(x);
    return (u & 0x80000000u) ? ~u : (u | 0x80000000u);
}
__device__ __forceinline__ float key_dec(unsigned k) {
    unsigned u = (k & 0x80000000u) ? (k ^ 0x80000000u) : ~k;
    return __uint_as_float(u);
}

// ---------------- prep: copy bank/flag, scatter f rows -------------------------
__global__ void prep_copy(const float* __restrict__ bank, const float* __restrict__ flag) {
    size_t total4 = (size_t)BANK_ROWS * CHANNEL / 4;
    const float4* src = (const float4*)bank;
    float4* dst = (float4*)g_bank;
    for (size_t i = (size_t)blockIdx.x * blockDim.x + threadIdx.x; i < total4;
         i += (size_t)gridDim.x * blockDim.x)
        dst[i] = src[i];
    for (int i = blockIdx.x * blockDim.x + threadIdx.x; i < BANK_ROWS;
         i += gridDim.x * blockDim.x)
        g_flag[i] = flag[i];
}

__global__ void prep_scatter(const float* __restrict__ f, const int* __restrict__ idx) {
    int n = blockIdx.x;
    int r = idx[n];
    const float4* src = (const float4*)(f + (size_t)n * CHANNEL);
    float4* dst = (float4*)(g_bank + (size_t)r * CHANNEL);
    dst[threadIdx.x] = src[threadIdx.x];   // 64 threads * float4 = 256 floats
    if (threadIdx.x == 0) g_flag[r] = 1.0f;
}

// ---------------- GEMM: g_ap[512, 41040] = f[512,256] @ g_bank[41040,256]^T ----
__global__ void gemm_kernel(const float* __restrict__ A) {
    __shared__ float As[16][64];
    __shared__ float Bs[16][64];
    int bm = blockIdx.y * 64, bn = blockIdx.x * 64;
    int tid = threadIdx.x;
    int tx = tid & 15, ty = tid >> 4;
    float acc[4][4] = {};

    int lrow = tid >> 2;
    int lk = (tid & 3) * 4;
    int brow = bn + lrow; if (brow >= BANK_ROWS) brow = BANK_ROWS - 1;
    const float* aptr = A + (size_t)(bm + lrow) * CHANNEL + lk;
    const float* bptr = g_bank + (size_t)brow * CHANNEL + lk;

    for (int k0 = 0; k0 < CHANNEL; k0 += 16) {
        float4 av = *(const float4*)(aptr + k0);
        float4 bv = *(const float4*)(bptr + k0);
        As[lk + 0][lrow] = av.x; As[lk + 1][lrow] = av.y;
        As[lk + 2][lrow] = av.z; As[lk + 3][lrow] = av.w;
        Bs[lk + 0][lrow] = bv.x; Bs[lk + 1][lrow] = bv.y;
        Bs[lk + 2][lrow] = bv.z; Bs[lk + 3][lrow] = bv.w;
        __syncthreads();
#pragma unroll
        for (int k = 0; k < 16; k++) {
            float4 a = *(const float4*)&As[k][ty * 4];
            float4 b = *(const float4*)&Bs[k][tx * 4];
            acc[0][0] += a.x * b.x; acc[0][1] += a.x * b.y; acc[0][2] += a.x * b.z; acc[0][3] += a.x * b.w;
            acc[1][0] += a.y * b.x; acc[1][1] += a.y * b.y; acc[1][2] += a.y * b.z; acc[1][3] += a.y * b.w;
            acc[2][0] += a.z * b.x; acc[2][1] += a.z * b.y; acc[2][2] += a.z * b.z; acc[2][3] += a.z * b.w;
            acc[3][0] += a.w * b.x; acc[3][1] += a.w * b.y; acc[3][2] += a.w * b.z; acc[3][3] += a.w * b.w;
        }
        __syncthreads();
    }
    int col = bn + tx * 4;
    if (col + 4 <= BANK_ROWS) {
#pragma unroll
        for (int i = 0; i < 4; i++) {
            float4 v = make_float4(acc[i][0], acc[i][1], acc[i][2], acc[i][3]);
            *(float4*)&g_ap[(size_t)(bm + ty * 4 + i) * BANK_ROWS + col] = v;
        }
    }
}

// ---------------- exact radix select (k-th smallest key) -----------------------
// mode 0: hard negatives, key = ~asc(ap[i]) (descending values)
// mode 1: random negatives, key = asc(rnd[i])
// mode 2: positives, i in [0,684), key = asc(ap[lab + 60*i])
__device__ unsigned radix_sel(int mode, int lab,
                              const float* __restrict__ ap,
                              const float* __restrict__ rnd,
                              int K, int* hist, int* s_coarse,
                              int* s_b, int* s_kk, int* p_need) {
    int tid = threadIdx.x;
    unsigned prefix = 0;
    int kk = K;
    int shift = 32;
#pragma unroll
    for (int pass = 0; pass < 3; pass++) {
        int bits = (pass < 2) ? 11 : 10;
        shift -= bits;
        int nb = 1 << bits;
        for (int i = tid; i < nb; i += 256) hist[i] = 0;
        __syncthreads();
        int count = (mode == 2) ? MEM_SIZE : BANK_ROWS;
        for (int i = tid; i < count; i += 256) {
            unsigned key;
            if (mode == 2) {
                int m = lab + CLASS_NUM * i;
                key = (g_flag[m] > 0.f) ? key_asc(ap[m]) : 0xFFFFFFFFu;
            } else {
                bool valid = ((i % CLASS_NUM) != lab) && (g_flag[i] > 0.f);
                if (mode == 0) key = valid ? ~key_asc(ap[i]) : 0xFFFFFFFFu;
                else           key = valid ? key_asc(rnd[i]) : 0xFFFFFFFFu;
            }
            if (pass == 0 || (key >> (shift + bits)) == prefix)
                atomicAdd(&hist[(key >> shift) & (nb - 1)], 1);
        }
        __syncthreads();
        int chunk = nb >> 8;
        int part = 0;
        for (int j = 0; j < chunk; j++) part += hist[tid * chunk + j];
        s_coarse[tid] = part;
        __syncthreads();
        if (tid == 0) {
            int cum = 0, cb = 0;
            for (; cb < 255; cb++) {
                if (cum + s_coarse[cb] >= kk) break;
                cum += s_coarse[cb];
            }
            int b = cb * chunk;
            for (;; b++) { if (cum + hist[b] >= kk) break; cum += hist[b]; }
            *s_b = b; *s_kk = kk - cum;
        }
        __syncthreads();
        prefix = (prefix << bits) | (unsigned)(*s_b);
        kk = *s_kk;
        __syncthreads();
    }
    *p_need = kk;
    return prefix;     // full 32-bit key of the K-th element
}

__device__ double block_red(double v, double* s_warp) {
#pragma unroll
    for (int o = 16; o; o >>= 1) v += __shfl_down_sync(0xffffffffu, v, o);
    int w = threadIdx.x >> 5;
    if ((threadIdx.x & 31) == 0) s_warp[w] = v;
    __syncthreads();
    double r = 0;
    if (threadIdx.x == 0) for (int i = 0; i < 8; i++) r += s_warp[i];
    __syncthreads();
    return r;          // valid on tid 0
}

// ---------------- per-row selection + loss partial -----------------------------
__global__ void select_kernel(const int* __restrict__ label,
                              const float* __restrict__ rand_neg) {
    __shared__ int    hist[2048];
    __shared__ int    s_coarse[256];
    __shared__ int    s_b, s_kk;
    __shared__ double s_warp[8];
    __shared__ float  s_posv[POS_NUM];
    __shared__ int    s_tie[256];
    __shared__ int    s_cnt;
    __shared__ double s_Sh, s_Sr;

    int n = blockIdx.x;
    int tid = threadIdx.x;
    int lab = label[n];
    const float* ap  = g_ap + (size_t)n * BANK_ROWS;
    const float* rnd = rand_neg + (size_t)n * BANK_ROWS;

    // ===== hard negatives: top-512 values =====
    int need_h;
    unsigned Th = radix_sel(0, lab, ap, rnd, NEG_NUM, hist, s_coarse, &s_b, &s_kk, &need_h);
    double loc = 0.0;
    for (int i = tid; i < BANK_ROWS; i += 256) {
        bool valid = ((i % CLASS_NUM) != lab) && (g_flag[i] > 0.f);
        if (valid) {
            float v = ap[i];
            if (~key_asc(v) < Th) loc += exp((double)v);
        }
    }
    double Sh = block_red(loc, s_warp);
    if (tid == 0) {
        float tv = key_dec(~Th);
        s_Sh = Sh + (double)need_h * exp((double)tv);
    }
    __syncthreads();

    // ===== random negatives: 512 smallest rand among negatives =====
    int need_r;
    unsigned Tr = radix_sel(1, lab, ap, rnd, NEG_NUM, hist, s_coarse, &s_b, &s_kk, &need_r);
    if (tid == 0) s_cnt = 0;
    __syncthreads();
    loc = 0.0;
    for (int i = tid; i < BANK_ROWS; i += 256) {
        bool valid = ((i % CLASS_NUM) != lab) && (g_flag[i] > 0.f);
        if (valid) {
            unsigned kr = key_asc(rnd[i]);
            if (kr < Tr) loc += exp((double)ap[i]);
            else if (kr == Tr) {
                int p = atomicAdd(&s_cnt, 1);
                if (p < 256) s_tie[p] = i;
            }
        }
    }
    double Sr = block_red(loc, s_warp);
    if (tid == 0) {
        int c = s_cnt < 256 ? s_cnt : 256;
        int take = need_r < c ? need_r : c;
        double add = 0.0;
        for (int t = 0; t < take; t++) {          // pick smallest column indices
            int best = 0x7fffffff, bi = -1;
            for (int j = 0; j < c; j++)
                if (s_tie[j] >= 0 && s_tie[j] < best) { best = s_tie[j]; bi = j; }
            s_tie[bi] = -1;
            add += exp((double)ap[best]);
        }
        s_Sr = Sr + add;
    }
    __syncthreads();

    // ===== positives: 128 smallest of 684 =====
    int need_p;
    unsigned Tp = radix_sel(2, lab, ap, rnd, POS_NUM, hist, s_coarse, &s_b, &s_kk, &need_p);
    if (tid == 0) s_cnt = 0;
    __syncthreads();
    for (int i = tid; i < MEM_SIZE; i += 256) {
        int m = lab + CLASS_NUM * i;
        if (g_flag[m] > 0.f) {
            float v = ap[m];
            if (key_asc(v) < Tp) {
                int p = atomicAdd(&s_cnt, 1);
                s_posv[p] = v;
            }
        }
    }
    __syncthreads();
    if (tid == 0) {
        float tv = key_dec(Tp);
        int base = s_cnt;                          // == POS_NUM - need_p
        for (int t = 0; t < need_p; t++) s_posv[base + t] = tv;
    }
    __syncthreads();

    // ===== loss partial =====
    double Shv = s_Sh, Srv = s_Sr;
    double l = 0.0;
    if (tid < POS_NUM) {
        double p = (double)s_posv[tid];
        double ep = exp(p);
        l = 2.0 * p - log(ep + Shv) - log(ep + Srv);
    }
    double tot = block_red(l, s_warp);
    if (tid == 0) g_partial[n] = tot;
}

// ---------------- finalize ------------------------------------------------------
__global__ void finalize_kernel(float* __restrict__ out) {
    __shared__ double s_warp[16];
    int tid = threadIdx.x;
    double v = g_partial[tid];
#pragma unroll
    for (int o = 16; o; o >>= 1) v += __shfl_down_sync(0xffffffffu, v, o);
    if ((tid & 31) == 0) s_warp[tid >> 5] = v;
    __syncthreads();
    if (tid == 0) {
        double t = 0;
        for (int i = 0; i < 16; i++) t += s_warp[i];
        out[0] = (float)(-t / (double)(BATCH * 2 * POS_NUM));
    }
}

// ---------------- launch --------------------------------------------------------
extern "C" void kernel_launch(void* const* d_in, const int* in_sizes, int n_in,
                              void* d_out, int out_size) {
    const float* f        = (const float*)d_in[0];
    const int*   label    = (const int*)d_in[1];
    const int*   enq      = (const int*)d_in[2];
    const float* bank     = (const float*)d_in[3];
    const float* flag     = (const float*)d_in[4];
    const float* rand_neg = (const float*)d_in[5];
    float* out = (float*)d_out;

    prep_copy<<<512, 256>>>(bank, flag);
    prep_scatter<<<BATCH, 64>>>(f, enq);
    dim3 g((BANK_ROWS + 63) / 64, BATCH / 64);
    gemm_kernel<<<g, 256>>>(f);
    select_kernel<<<BATCH, 256>>>(label, rand_neg);
    finalize_kernel<<<1, 512>>>(out);
}

// round 7
// speedup vs baseline: 3.2703x; 3.2703x over previous
#include <cuda_runtime.h>
#include <cuda_bf16.h>
#include <math.h>
#include <stdint.h>

#define CHANNEL   256
#define MEM_SIZE  684
#define POS_NUM   128
#define NEG_NUM   512
#define CLASS_NUM 60
#define BANK_ROWS 41040          // MEM_SIZE * CLASS_NUM
#define BANK_PAD  41088          // 321 * 128
#define BATCH     512

// ---------------- scratch (static device globals) ------------------------------
__device__ __nv_bfloat16 g_bank_bf[(size_t)BANK_PAD * CHANNEL];   // 21 MB
__device__ __nv_bfloat16 g_f_bf[(size_t)BATCH * CHANNEL];
__device__ float  g_flag[BANK_ROWS];
__device__ float  g_ap[(size_t)BATCH * BANK_ROWS];                // 84 MB
__device__ double g_partial[BATCH];

// ---------------- helpers ------------------------------------------------------
__device__ __forceinline__ uint32_t smem_u32(const void* p) {
    uint32_t a;
    asm("{ .reg .u64 t; cvta.to.shared.u64 t, %1; cvt.u32.u64 %0, t; }" : "=r"(a) : "l"(p));
    return a;
}

// ---------------- order-preserving float <-> uint key --------------------------
__device__ __forceinline__ unsigned key_asc(float x) {
    unsigned u = __float_as_uint(x);
    return (u & 0x80000000u) ? ~u : (u | 0x80000000u);
}
__device__ __forceinline__ float key_dec(unsigned k) {
    unsigned u = (k & 0x80000000u) ? (k ^ 0x80000000u) : ~k;
    return __uint_as_float(u);
}

// ---------------- prep: bank -> bf16 (padded), flag copy, f -> bf16 ------------
__global__ void convert_kernel(const float* __restrict__ bank,
                               const float* __restrict__ flag,
                               const float* __restrict__ f) {
    size_t tid = (size_t)blockIdx.x * blockDim.x + threadIdx.x;
    size_t stride = (size_t)gridDim.x * blockDim.x;
    size_t total4 = (size_t)BANK_PAD * CHANNEL / 4;
    size_t real4  = (size_t)BANK_ROWS * CHANNEL / 4;
    for (size_t i = tid; i < total4; i += stride) {
        float4 v = make_float4(0.f, 0.f, 0.f, 0.f);
        if (i < real4) v = ((const float4*)bank)[i];
        __nv_bfloat162 lo(__float2bfloat16(v.x), __float2bfloat16(v.y));
        __nv_bfloat162 hi(__float2bfloat16(v.z), __float2bfloat16(v.w));
        ((__nv_bfloat162*)g_bank_bf)[2 * i]     = lo;
        ((__nv_bfloat162*)g_bank_bf)[2 * i + 1] = hi;
    }
    for (size_t i = tid; i < BANK_ROWS; i += stride) g_flag[i] = flag[i];
    size_t f4 = (size_t)BATCH * CHANNEL / 4;
    for (size_t i = tid; i < f4; i += stride) {
        float4 v = ((const float4*)f)[i];
        __nv_bfloat162 lo(__float2bfloat16(v.x), __float2bfloat16(v.y));
        __nv_bfloat162 hi(__float2bfloat16(v.z), __float2bfloat16(v.w));
        ((__nv_bfloat162*)g_f_bf)[2 * i]     = lo;
        ((__nv_bfloat162*)g_f_bf)[2 * i + 1] = hi;
    }
}

__global__ void scatter_kernel(const float* __restrict__ f, const int* __restrict__ idx) {
    int n = blockIdx.x;
    int r = idx[n];
    float4 v = ((const float4*)(f + (size_t)n * CHANNEL))[threadIdx.x];
    __nv_bfloat162 lo(__float2bfloat16(v.x), __float2bfloat16(v.y));
    __nv_bfloat162 hi(__float2bfloat16(v.z), __float2bfloat16(v.w));
    __nv_bfloat162* dst = (__nv_bfloat162*)(g_bank_bf + (size_t)r * CHANNEL) + 2 * threadIdx.x;
    dst[0] = lo; dst[1] = hi;
    if (threadIdx.x == 0) g_flag[r] = 1.0f;
}

// ---------------- mma.sync bf16 GEMM: g_ap[512,41040] = f @ bank^T -------------
// Block 128x128, 256 threads (8 warps, 2x4), warp tile 64x32, K chunks of 64.
#define SMEM_STRIDE 72

__global__ void __launch_bounds__(256, 2) gemm_mma_kernel() {
    __shared__ __nv_bfloat16 As[128][SMEM_STRIDE];
    __shared__ __nv_bfloat16 Bs[128][SMEM_STRIDE];

    int tid = threadIdx.x, lane = tid & 31, wid = tid >> 5;
    int wm = wid >> 2;           // 0..1   (64 rows each)
    int wn = wid & 3;            // 0..3   (32 cols each)
    int bm = blockIdx.y * 128;   // batch tile
    int bn = blockIdx.x * 128;   // bank-row tile

    const __nv_bfloat16* Ag = g_f_bf    + (size_t)bm * CHANNEL;
    const __nv_bfloat16* Bg = g_bank_bf + (size_t)bn * CHANNEL;

    float acc[4][4][4];
#pragma unroll
    for (int i = 0; i < 4; i++)
#pragma unroll
        for (int j = 0; j < 4; j++)
#pragma unroll
            for (int k = 0; k < 4; k++) acc[i][j][k] = 0.f;

    int lrow = tid >> 3;            // 0..31 for loads
    int lcol = (tid & 7) * 8;       // vec8 column

#pragma unroll
    for (int kc = 0; kc < 4; kc++) {
        int k0 = kc * 64;
        // ---- load 128x64 A and B chunks (vec8 bf16 = uint4) ----
#pragma unroll
        for (int it = 0; it < 4; it++) {
            int row = lrow + it * 32;
            *(uint4*)&As[row][lcol] = *(const uint4*)(Ag + (size_t)row * CHANNEL + k0 + lcol);
            *(uint4*)&Bs[row][lcol] = *(const uint4*)(Bg + (size_t)row * CHANNEL + k0 + lcol);
        }
        __syncthreads();

#pragma unroll
        for (int ks = 0; ks < 4; ks++) {
            int kk = ks * 16;
            uint32_t af[4][4], bfr[4][2];
            // A fragments: 4 m-tiles of 16x16
#pragma unroll
            for (int mt = 0; mt < 4; mt++) {
                int row = wm * 64 + mt * 16 + (lane & 15);
                int col = kk + (lane >> 4) * 8;
                uint32_t a = smem_u32(&As[row][col]);
                asm volatile(
                    "ldmatrix.sync.aligned.m8n8.x4.shared.b16 {%0,%1,%2,%3}, [%4];"
                    : "=r"(af[mt][0]), "=r"(af[mt][1]), "=r"(af[mt][2]), "=r"(af[mt][3])
                    : "r"(a));
            }
            // B fragments: 4 n-tiles of 8 (two x4 loads, each covers 2 n-tiles)
#pragma unroll
            for (int g = 0; g < 2; g++) {
                int ntile = g * 2 + (lane >> 4);
                int khalf = (lane >> 3) & 1;
                int row = wn * 32 + ntile * 8 + (lane & 7);
                int col = kk + khalf * 8;
                uint32_t a = smem_u32(&Bs[row][col]);
                uint32_t b0, b1, b2, b3;
                asm volatile(
                    "ldmatrix.sync.aligned.m8n8.x4.shared.b16 {%0,%1,%2,%3}, [%4];"
                    : "=r"(b0), "=r"(b1), "=r"(b2), "=r"(b3) : "r"(a));
                bfr[g * 2][0] = b0; bfr[g * 2][1] = b1;
                bfr[g * 2 + 1][0] = b2; bfr[g * 2 + 1][1] = b3;
            }
#pragma unroll
            for (int mt = 0; mt < 4; mt++)
#pragma unroll
                for (int nt = 0; nt < 4; nt++) {
                    asm volatile(
                        "mma.sync.aligned.m16n8k16.row.col.f32.bf16.bf16.f32 "
                        "{%0,%1,%2,%3}, {%4,%5,%6,%7}, {%8,%9}, {%0,%1,%2,%3};"
                        : "+f"(acc[mt][nt][0]), "+f"(acc[mt][nt][1]),
                          "+f"(acc[mt][nt][2]), "+f"(acc[mt][nt][3])
                        : "r"(af[mt][0]), "r"(af[mt][1]), "r"(af[mt][2]), "r"(af[mt][3]),
                          "r"(bfr[nt][0]), "r"(bfr[nt][1]));
                }
        }
        __syncthreads();
    }

    // ---- epilogue: guarded float2 stores straight from accumulators ----
    int r0 = lane >> 2;
    int c0 = (lane & 3) * 2;
#pragma unroll
    for (int mt = 0; mt < 4; mt++) {
        int row = bm + wm * 64 + mt * 16 + r0;
#pragma unroll
        for (int nt = 0; nt < 4; nt++) {
            int col = bn + wn * 32 + nt * 8 + c0;
            if (col < BANK_ROWS) {
                float* d = g_ap + (size_t)row * BANK_ROWS + col;
                *(float2*)d = make_float2(acc[mt][nt][0], acc[mt][nt][1]);
                *(float2*)(d + (size_t)8 * BANK_ROWS) = make_float2(acc[mt][nt][2], acc[mt][nt][3]);
            }
        }
    }
}

// ---------------- exact radix select (512 threads) -----------------------------
#define SEL_T 512
// mode 0: hard negatives, key = ~asc(ap[i]); mode 1: rand, key = asc(rnd[i]);
// mode 2: positives, key = asc(ap[lab + 60*i])
__device__ unsigned radix_sel(int mode, int lab,
                              const float* __restrict__ ap,
                              const float* __restrict__ rnd,
                              const unsigned* __restrict__ s_mask,
                              int K, int* hist, int* s_coarse,
                              int* s_b, int* s_kk, int* p_need) {
    int tid = threadIdx.x;
    unsigned prefix = 0;
    int kk = K;
    int shift = 32;
#pragma unroll
    for (int pass = 0; pass < 3; pass++) {
        int bits = (pass < 2) ? 11 : 10;
        shift -= bits;
        int nb = 1 << bits;
        for (int i = tid; i < nb; i += SEL_T) hist[i] = 0;
        __syncthreads();
        int count = (mode == 2) ? MEM_SIZE : BANK_ROWS;
        for (int i = tid; i < count; i += SEL_T) {
            unsigned key;
            if (mode == 2) {
                int mm = lab + CLASS_NUM * i;
                key = (g_flag[mm] > 0.f) ? key_asc(ap[mm]) : 0xFFFFFFFFu;
            } else {
                bool valid = (s_mask[i >> 5] >> (i & 31)) & 1u;
                if (mode == 0) key = valid ? ~key_asc(ap[i]) : 0xFFFFFFFFu;
                else           key = valid ? key_asc(rnd[i]) : 0xFFFFFFFFu;
            }
            if (pass == 0 || (key >> (shift + bits)) == prefix)
                atomicAdd(&hist[(key >> shift) & (nb - 1)], 1);
        }
        __syncthreads();
        int chunk = nb >> 8;
        if (tid < 256) {
            int part = 0;
            for (int j = 0; j < chunk; j++) part += hist[tid * chunk + j];
            s_coarse[tid] = part;
        }
        __syncthreads();
        if (tid == 0) {
            int cum = 0, cb = 0;
            for (; cb < 255; cb++) {
                if (cum + s_coarse[cb] >= kk) break;
                cum += s_coarse[cb];
            }
            int b = cb * chunk;
            for (;; b++) { if (cum + hist[b] >= kk) break; cum += hist[b]; }
            *s_b = b; *s_kk = kk - cum;
        }
        __syncthreads();
        prefix = (prefix << bits) | (unsigned)(*s_b);
        kk = *s_kk;
        __syncthreads();
    }
    *p_need = kk;
    return prefix;
}

__device__ double block_red(double v, double* s_warp) {
#pragma unroll
    for (int o = 16; o; o >>= 1) v += __shfl_down_sync(0xffffffffu, v, o);
    int w = threadIdx.x >> 5;
    if ((threadIdx.x & 31) == 0) s_warp[w] = v;
    __syncthreads();
    double r = 0;
    if (threadIdx.x == 0) for (int i = 0; i < 16; i++) r += s_warp[i];
    __syncthreads();
    return r;
}

// ---------------- per-row selection + loss partial -----------------------------
__global__ void __launch_bounds__(SEL_T) select_kernel(const int* __restrict__ label,
                                                       const float* __restrict__ rand_neg) {
    __shared__ int      hist[2048];
    __shared__ int      s_coarse[256];
    __shared__ unsigned s_mask[(BANK_ROWS + 31) / 32];
    __shared__ int      s_b, s_kk;
    __shared__ double   s_warp[16];
    __shared__ float    s_posv[POS_NUM];
    __shared__ int      s_tie[256];
    __shared__ int      s_cnt;
    __shared__ double   s_Sh, s_Sr;

    int n = blockIdx.x;
    int tid = threadIdx.x;
    int lab = label[n];
    const float* ap  = g_ap + (size_t)n * BANK_ROWS;
    const float* rnd = rand_neg + (size_t)n * BANK_ROWS;

    // build neg-valid bitmask: flag>0 && (i%60 != lab)
    const int NW = (BANK_ROWS + 31) / 32;
    for (int w = tid; w < NW; w += SEL_T) {
        unsigned m = 0;
        int base = w * 32;
        int lim = BANK_ROWS - base; if (lim > 32) lim = 32;
        for (int e = 0; e < lim; e++) {
            int i = base + e;
            if ((i % CLASS_NUM) != lab && g_flag[i] > 0.f) m |= (1u << e);
        }
        s_mask[w] = m;
    }
    __syncthreads();

    // ===== hard negatives: top-512 values =====
    int need_h;
    unsigned Th = radix_sel(0, lab, ap, rnd, s_mask, NEG_NUM, hist, s_coarse, &s_b, &s_kk, &need_h);
    double loc = 0.0;
    for (int i = tid; i < BANK_ROWS; i += SEL_T) {
        if ((s_mask[i >> 5] >> (i & 31)) & 1u) {
            float v = ap[i];
            if (~key_asc(v) < Th) loc += (double)expf(v);
        }
    }
    double Sh = block_red(loc, s_warp);
    if (tid == 0) {
        float tv = key_dec(~Th);
        s_Sh = Sh + (double)need_h * (double)expf(tv);
    }
    __syncthreads();

    // ===== random negatives: 512 smallest rand among negatives =====
    int need_r;
    unsigned Tr = radix_sel(1, lab, ap, rnd, s_mask, NEG_NUM, hist, s_coarse, &s_b, &s_kk, &need_r);
    if (tid == 0) s_cnt = 0;
    __syncthreads();
    loc = 0.0;
    for (int i = tid; i < BANK_ROWS; i += SEL_T) {
        if ((s_mask[i >> 5] >> (i & 31)) & 1u) {
            unsigned kr = key_asc(rnd[i]);
            if (kr < Tr) loc += (double)expf(ap[i]);
            else if (kr == Tr) {
                int p = atomicAdd(&s_cnt, 1);
                if (p < 256) s_tie[p] = i;
            }
        }
    }
    double Sr = block_red(loc, s_warp);
    if (tid == 0) {
        int c = s_cnt < 256 ? s_cnt : 256;
        int take = need_r < c ? need_r : c;
        double add = 0.0;
        for (int t = 0; t < take; t++) {
            int best = 0x7fffffff, bi = -1;
            for (int j = 0; j < c; j++)
                if (s_tie[j] >= 0 && s_tie[j] < best) { best = s_tie[j]; bi = j; }
            s_tie[bi] = -1;
            add += (double)expf(ap[best]);
        }
        s_Sr = Sr + add;
    }
    __syncthreads();

    // ===== positives: 128 smallest of 684 =====
    int need_p;
    unsigned Tp = radix_sel(2, lab, ap, rnd, s_mask, POS_NUM, hist, s_coarse, &s_b, &s_kk, &need_p);
    if (tid == 0) s_cnt = 0;
    __syncthreads();
    for (int i = tid; i < MEM_SIZE; i += SEL_T) {
        int m = lab + CLASS_NUM * i;
        if (g_flag[m] > 0.f) {
            float v = ap[m];
            if (key_asc(v) < Tp) {
                int p = atomicAdd(&s_cnt, 1);
                s_posv[p] = v;
            }
        }
    }
    __syncthreads();
    if (tid == 0) {
        float tv = key_dec(Tp);
        int base = s_cnt;
        for (int t = 0; t < need_p; t++) s_posv[base + t] = tv;
    }
    __syncthreads();

    // ===== loss partial =====
    double Shv = s_Sh, Srv = s_Sr;
    double l = 0.0;
    if (tid < POS_NUM) {
        double p = (double)s_posv[tid];
        double ep = exp(p);
        l = 2.0 * p - log(ep + Shv) - log(ep + Srv);
    }
    double tot = block_red(l, s_warp);
    if (tid == 0) g_partial[n] = tot;
}

// ---------------- finalize ------------------------------------------------------
__global__ void finalize_kernel(float* __restrict__ out) {
    __shared__ double s_warp[16];
    int tid = threadIdx.x;
    double v = g_partial[tid];
#pragma unroll
    for (int o = 16; o; o >>= 1) v += __shfl_down_sync(0xffffffffu, v, o);
    if ((tid & 31) == 0) s_warp[tid >> 5] = v;
    __syncthreads();
    if (tid == 0) {
        double t = 0;
        for (int i = 0; i < 16; i++) t += s_warp[i];
        out[0] = (float)(-t / (double)(BATCH * 2 * POS_NUM));
    }
}

// ---------------- launch --------------------------------------------------------
extern "C" void kernel_launch(void* const* d_in, const int* in_sizes, int n_in,
                              void* d_out, int out_size) {
    const float* f        = (const float*)d_in[0];
    const int*   label    = (const int*)d_in[1];
    const int*   enq      = (const int*)d_in[2];
    const float* bank     = (const float*)d_in[3];
    const float* flag     = (const float*)d_in[4];
    const float* rand_neg = (const float*)d_in[5];
    float* out = (float*)d_out;

    convert_kernel<<<1024, 256>>>(bank, flag, f);
    scatter_kernel<<<BATCH, 64>>>(f, enq);
    dim3 g(BANK_PAD / 128, BATCH / 128);
    gemm_mma_kernel<<<g, 256>>>();
    select_kernel<<<BATCH, SEL_T>>>(label, rand_neg);
    finalize_kernel<<<1, 512>>>(out);
}